// round 10
// baseline (speedup 1.0000x reference)
#include <cuda_runtime.h>
#include <math.h>
#include <stdint.h>

// Shape fixed by reference: x,y = [16, 3, 512, 512] f32
#define BATCH   16
#define HDIM    512
#define WDIM    512
#define RSTRIP  16                    // output rows per block
#define STRIPS  (HDIM / RSTRIP)       // 32
#define NBLOCKS (BATCH * STRIPS)      // 512
#define THREADS 128                   // one float4 column per thread
#define ROWSIN  (RSTRIP + 6)          // 22 streamed rows
#define NS      3                     // smem ring slots (2 rows in flight)
#define SLOT_FLOATS (6 * WDIM)        // x0,x1,x2,y0,y1,y2 segments = 3072 floats
#define EPSV    1e-6f

__device__ float        g_partials[NBLOCKS];
__device__ unsigned int g_count;     // zero-init at load; reset by last block

__device__ __forceinline__ void cpa16(uint32_t saddr, const float* gaddr, int srcsz) {
    asm volatile("cp.async.cg.shared.global [%0], [%1], 16, %2;"
                 :: "r"(saddr), "l"(gaddr), "r"(srcsz));
}
__device__ __forceinline__ void cp_commit() { asm volatile("cp.async.commit_group;"); }
__device__ __forceinline__ void cp_wait1()  { asm volatile("cp.async.wait_group 1;" ::: "memory"); }

__global__ __launch_bounds__(THREADS, 4) void charb_kernel(
    const float* __restrict__ x, const float* __restrict__ y,
    float* __restrict__ out)
{
    __shared__ float stage[NS * SLOT_FLOATS];   // 36 KB, static (under 48 KB cap)
    __shared__ float warpsum[4];
    __shared__ bool  isLast;

    const int tid  = threadIdx.x;
    const int lane = tid & 31;
    const int c0   = tid << 2;                // this thread's 4 columns

    const int blk = blockIdx.x;
    const int b   = blk / STRIPS;
    const int s   = blk % STRIPS;
    const int h0  = s * RSTRIP;
    const bool rev = (s & 1);                 // serpentine: odd strips bottom-up
    const int rbase = rev ? (h0 + RSTRIP + 2) : (h0 - 3);
    const int rstep = rev ? -1 : 1;

    const bool isL = (lane == 0);
    const bool isR = (lane == 31);
    const int  hc  = isL ? (c0 - 4) : (c0 + 4);        // halo float4 (edge lanes)
    const bool haloOk = (isL && c0 >= 4) || (isR && c0 + 4 < WDIM);

    const size_t plane = (size_t)HDIM * WDIM;
    const float* xb = x + (size_t)b * 3 * plane + c0;  // pre-offset by column
    const float* yb = y + (size_t)b * 3 * plane + c0;

    const uint32_t sbase = (uint32_t)__cvta_generic_to_shared(stage);

    // ---- prologue: issue rows 0..1 (one commit group each) ----
    #pragma unroll
    for (int i = 0; i < 2; ++i) {
        const int r  = rbase + rstep * i;
        const bool ok = (r >= 0) && (r < HDIM);
        const int rc  = ok ? r : 0;
        const int sz  = ok ? 16 : 0;                    // zfill out-of-image rows
        const uint32_t sa = sbase + (uint32_t)(i * SLOT_FLOATS * 4 + tid * 16);
        const float* gx = xb + (size_t)rc * WDIM;
        const float* gy = yb + (size_t)rc * WDIM;
        cpa16(sa + 0 * 2048, gx,             sz);
        cpa16(sa + 1 * 2048, gx + plane,     sz);
        cpa16(sa + 2 * 2048, gx + 2 * plane, sz);
        cpa16(sa + 3 * 2048, gy,             sz);
        cpa16(sa + 4 * 2048, gy + plane,     sz);
        cpa16(sa + 5 * 2048, gy + 2 * plane, sz);
        cp_commit();
    }

    const float4 z4 = make_float4(0.f, 0.f, 0.f, 0.f);
    float4 r0 = z4, r1 = z4, r2 = z4, r3 = z4, r4 = z4, r5 = z4;  // vertical ring
    float4 vs = z4;
    float  acc = 0.f;

    int slot = 0, wslot = 2;   // consume slot; write slot (precomputed mod-3 walk)

    #pragma unroll 1
    for (int i = 0; i < ROWSIN; ++i) {
        cp_wait1();          // row i committed (this thread's copies)
        __syncthreads();     // all threads' copies visible; WAR gate for slot reuse

        // issue row i+2 into wslot (read finished by all threads in iter i-1)
        {
            const int ni = i + 2;
            if (ni < ROWSIN) {
                const int r  = rbase + rstep * ni;
                const bool ok = (r >= 0) && (r < HDIM);
                const int rc  = ok ? r : 0;
                const int sz  = ok ? 16 : 0;
                const uint32_t sa = sbase + (uint32_t)(wslot * SLOT_FLOATS * 4 + tid * 16);
                const float* gx = xb + (size_t)rc * WDIM;
                const float* gy = yb + (size_t)rc * WDIM;
                cpa16(sa + 0 * 2048, gx,             sz);
                cpa16(sa + 1 * 2048, gx + plane,     sz);
                cpa16(sa + 2 * 2048, gx + 2 * plane, sz);
                cpa16(sa + 3 * 2048, gy,             sz);
                cpa16(sa + 4 * 2048, gy + plane,     sz);
                cpa16(sa + 5 * 2048, gy + 2 * plane, sz);
            }
            cp_commit();     // uniform group accounting (may be empty)
        }

        // ---- consume row i from 'slot' ----
        const float* sp = stage + slot * SLOT_FLOATS;
        const float4 xa = *(const float4*)(sp +    0 + c0);
        const float4 xm = *(const float4*)(sp +  512 + c0);
        const float4 xc = *(const float4*)(sp + 1024 + c0);
        const float4 ya = *(const float4*)(sp + 1536 + c0);
        const float4 ym = *(const float4*)(sp + 2048 + c0);
        const float4 yc = *(const float4*)(sp + 2560 + c0);

        float4 d;
        d.x = (xa.x - ya.x) + (xm.x - ym.x) + (xc.x - yc.x);
        d.y = (xa.y - ya.y) + (xm.y - ym.y) + (xc.y - yc.y);
        d.z = (xa.z - ya.z) + (xm.z - ym.z) + (xc.z - yc.z);
        d.w = (xa.w - ya.w) + (xm.w - ym.w) + (xc.w - yc.w);

        float4 dh = z4;                       // edge-lane halo diff (from smem)
        if (haloOk) {
            const float* hp = sp + hc;
            const float4 ha = *(const float4*)(hp);
            const float4 hm = *(const float4*)(hp +  512);
            const float4 hcv= *(const float4*)(hp + 1024);
            const float4 pa = *(const float4*)(hp + 1536);
            const float4 pm = *(const float4*)(hp + 2048);
            const float4 pc = *(const float4*)(hp + 2560);
            dh.x = (ha.x - pa.x) + (hm.x - pm.x) + (hcv.x - pc.x);
            dh.y = (ha.y - pa.y) + (hm.y - pm.y) + (hcv.y - pc.y);
            dh.z = (ha.z - pa.z) + (hm.z - pm.z) + (hcv.z - pc.z);
            dh.w = (ha.w - pa.w) + (hm.w - pm.w) + (hcv.w - pc.w);
        }

        // horizontal neighbors via shuffles
        float py = __shfl_up_sync(0xffffffffu, d.y, 1);
        float pz = __shfl_up_sync(0xffffffffu, d.z, 1);
        float pw = __shfl_up_sync(0xffffffffu, d.w, 1);
        float nx = __shfl_down_sync(0xffffffffu, d.x, 1);
        float ny = __shfl_down_sync(0xffffffffu, d.y, 1);
        float nz = __shfl_down_sync(0xffffffffu, d.z, 1);
        if (isL) { py = dh.y; pz = dh.z; pw = dh.w; }
        if (isR) { nx = dh.x; ny = dh.y; nz = dh.z; }

        // horizontal 7-tap sums for this thread's 4 columns
        float4 hsum;
        hsum.x = ((py + pz) + (pw + d.x)) + ((d.y + d.z) + d.w);
        hsum.y = hsum.x - py + nx;
        hsum.z = hsum.y - pz + ny;
        hsum.w = hsum.z - pw + nz;

        // vertical running 7-row sum + Charbonnier
        vs.x += hsum.x; vs.y += hsum.y; vs.z += hsum.z; vs.w += hsum.w;
        if (i >= 6) {
            const float inv = 1.f / 49.f;
            const float v0 = vs.x * inv, v1 = vs.y * inv;
            const float v2 = vs.z * inv, v3 = vs.w * inv;
            acc += (sqrtf(v0 * v0 + EPSV) + sqrtf(v1 * v1 + EPSV))
                 + (sqrtf(v2 * v2 + EPSV) + sqrtf(v3 * v3 + EPSV));
            vs.x -= r0.x; vs.y -= r0.y; vs.z -= r0.z; vs.w -= r0.w;
        }
        r0 = r1; r1 = r2; r2 = r3; r3 = r4; r4 = r5; r5 = hsum;

        slot  = (slot  == 2) ? 0 : slot  + 1;
        wslot = (wslot == 2) ? 0 : wslot + 1;
    }

    // block reduction (4 warps)
    #pragma unroll
    for (int off = 16; off; off >>= 1) acc += __shfl_xor_sync(0xffffffffu, acc, off);
    if (lane == 0) warpsum[tid >> 5] = acc;
    __syncthreads();
    if (tid < 32) {
        float v = (lane < 4) ? warpsum[lane] : 0.f;
        v += __shfl_xor_sync(0xffffffffu, v, 2);
        v += __shfl_xor_sync(0xffffffffu, v, 1);
        if (tid == 0) {
            g_partials[blk] = v;
            __threadfence();
            const unsigned int t = atomicAdd(&g_count, 1u);
            isLast = (t == NBLOCKS - 1);
        }
    }
    __syncthreads();

    // last-arriving block folds the 512 partials -> scalar (deterministic order)
    if (isLast) {
        __threadfence();
        float v = (g_partials[tid]       + g_partials[tid + 128])
                + (g_partials[tid + 256] + g_partials[tid + 384]);
        #pragma unroll
        for (int off = 16; off; off >>= 1) v += __shfl_xor_sync(0xffffffffu, v, off);
        if (lane == 0) warpsum[tid >> 5] = v;
        __syncthreads();
        if (tid < 32) {
            float v2 = (lane < 4) ? warpsum[lane] : 0.f;
            v2 += __shfl_xor_sync(0xffffffffu, v2, 2);
            v2 += __shfl_xor_sync(0xffffffffu, v2, 1);
            if (tid == 0) {
                out[0]  = v2 / (float)((size_t)BATCH * HDIM * WDIM);
                g_count = 0u;
            }
        }
    }
}

extern "C" void kernel_launch(void* const* d_in, const int* in_sizes, int n_in,
                              void* d_out, int out_size)
{
    (void)in_sizes; (void)n_in; (void)out_size;
    const float* x = (const float*)d_in[0];
    const float* y = (const float*)d_in[1];
    float* out = (float*)d_out;

    charb_kernel<<<NBLOCKS, THREADS>>>(x, y, out);
}